// round 15
// baseline (speedup 1.0000x reference)
#include <cuda_runtime.h>
#include <math_constants.h>

#define N_SAMPLES 4096
#define D_IN      1024
#define D_OUT     256
#define GRID      296          // 148 SMs x occ 2, all co-resident
#define N_FC      128          // FC work items (4 n-tiles x 32 m-tiles)
#define N_TILES   528          // upper-triangle 128x128 dist tiles

// ---------------- persistent device scratch (no allocations allowed) --------
__device__ float    g_h [N_SAMPLES * D_OUT];   // projected features, 4 MB
__device__ float    g_sq[N_SAMPLES];           // ||h_i||^2 (atomic-accumulated)
__device__ unsigned g_hp[N_SAMPLES];           // enc(max same-class  of  sq_o-2g)
__device__ unsigned g_hn[N_SAMPLES];           // enc(max diff-class  of -(sq_o-2g))
__device__ unsigned g_fc_done[32];             // per-128-row-group FC completion (0..4)
__device__ unsigned g_ticket;                  // dist tile ticket counter
__device__ unsigned g_done;                    // finished-block counter
// all zero-initialized; the loss block resets them to zero at the end of every
// launch, so graph replays always start clean.

__device__ __forceinline__ int get_cls(const void* T, int i, int is64) {
    return is64 ? (int)((const long long*)T)[i] : ((const int*)T)[i];
}

// order-preserving float <-> uint encoding (handles negatives / inf)
__device__ __forceinline__ unsigned enc_f(float f) {
    unsigned b = __float_as_uint(f);
    return (b & 0x80000000u) ? ~b : (b | 0x80000000u);
}
__device__ __forceinline__ float dec_f(unsigned u) {
    return __uint_as_float((u & 0x80000000u) ? (u ^ 0x80000000u) : ~u);
}

// tf32 warp mma: D = A(16x8) * B(8x8) + D, fp32 accumulate
__device__ __forceinline__ void mma_tf32(float* d, const unsigned* a,
                                         unsigned b0, unsigned b1) {
    asm volatile(
        "mma.sync.aligned.m16n8k8.row.col.f32.tf32.tf32.f32 "
        "{%0,%1,%2,%3}, {%4,%5,%6,%7}, {%8,%9}, {%0,%1,%2,%3};"
        : "+f"(d[0]), "+f"(d[1]), "+f"(d[2]), "+f"(d[3])
        : "r"(a[0]), "r"(a[1]), "r"(a[2]), "r"(a[3]), "r"(b0), "r"(b1));
}

__device__ __forceinline__ unsigned tf32_hi(float x) {
    unsigned r;
    asm("cvt.rna.tf32.f32 %0, %1;" : "=r"(r) : "f"(x));
    return r;
}

__device__ __forceinline__ void ldsm4(unsigned* r, unsigned addr) {
    asm volatile("ldmatrix.sync.aligned.m8n8.x4.shared.b16 {%0,%1,%2,%3}, [%4];"
                 : "=r"(r[0]), "=r"(r[1]), "=r"(r[2]), "=r"(r[3]) : "r"(addr));
}

// cp.async (16B, L2-only .cg path -> also bypasses stale L1 on consume)
__device__ __forceinline__ void cp16(const void* smem_dst, const void* gmem_src) {
    unsigned s = (unsigned)__cvta_generic_to_shared(smem_dst);
    asm volatile("cp.async.cg.shared.global [%0], [%1], 16;" :: "r"(s), "l"(gmem_src));
}
#define CP_COMMIT() asm volatile("cp.async.commit_group;" ::: "memory")
#define CP_WAIT1()  asm volatile("cp.async.wait_group 1;" ::: "memory")
#define CP_WAIT0()  asm volatile("cp.async.wait_group 0;" ::: "memory")

// smem layouts (word offsets into the dynamic buffer)
#define D_BK    32
#define D_TW    (128 * 36)
#define SM_WORDS (4 * D_TW + 128 + 128)
#define SM_BYTES (SM_WORDS * 4)

#define AS(b, r, c) dsm[(b) * D_TW + (r) * 36 + (c)]
#define BS(b, r, c) dsm[2 * D_TW + (b) * D_TW + (r) * 36 + (c)]

#define FC_BK  32
#define FC_XW  (128 * 36)
#define FC_WW  (FC_BK * 72)
#define XS(b, r, c) dsm[(b) * FC_XW + (r) * 36 + (c)]
#define WS(b, k, c) dsm[2 * FC_XW + (b) * FC_WW + (k) * 72 + (c)]

__global__ __launch_bounds__(256, 2)
void k_fused(const float* __restrict__ x, const float* __restrict__ W,
             const float* __restrict__ bias, const void* __restrict__ targets,
             float* __restrict__ out) {
    extern __shared__ float dsm[];
    float*   s_sq  = &dsm[4 * D_TW];
    int*     s_cl  = (int*)&dsm[4 * D_TW + 128];
    unsigned sbase = (unsigned)__cvta_generic_to_shared(dsm);
    __shared__ unsigned s_u;
    __shared__ int      s_flag;

    int tid  = threadIdx.x;
    int lane = tid & 31;
    int wid  = tid >> 5;
    int wm   = wid & 3;
    int wn   = wid >> 2;
    int g    = lane >> 2;
    int t    = lane & 3;
    int l7   = lane & 7;
    int bid  = blockIdx.x;

    // ---- per-block targets dtype detect (cheap, L2-resident after block 0) ----
    {
        const unsigned* tw = (const unsigned*)targets;
        unsigned acc = 0;
        for (int i = tid; i < 2048; i += 256) acc |= tw[2 * i + 1];
        #pragma unroll
        for (int o = 16; o; o >>= 1) acc |= __shfl_xor_sync(0xffffffffu, acc, o);
        if (tid == 0) s_flag = 1;
        __syncthreads();
        if (lane == 0 && acc != 0u) s_flag = 0;
        __syncthreads();
    }
    int is64 = s_flag;

    // ldmatrix lane offsets (word units, buffer 0, kk=0) — shared by both phases
    int aoff[2], boff[4];
    #pragma unroll
    for (int tm = 0; tm < 2; tm++)
        aoff[tm] = (wm * 32 + tm * 16 + ((lane >> 3) & 1) * 8 + l7) * 36 + (lane >> 4) * 4;
    #pragma unroll
    for (int tp = 0; tp < 4; tp++)
        boff[tp] = 2 * D_TW + (wn * 64 + tp * 16 + ((lane >> 4) & 1) * 8 + l7) * 36
                 + ((lane >> 3) & 1) * 4;

    // ================= phase 1: FC (blocks 0..127) ===========================
    if (bid < N_FC) {
        int n0 = (bid & 3) * 64;
        int m0 = (bid >> 2) * 128;

        float acc[2][4][4];
        #pragma unroll
        for (int tm = 0; tm < 2; tm++)
            #pragma unroll
            for (int tn = 0; tn < 4; tn++)
                #pragma unroll
                for (int c = 0; c < 4; c++) acc[tm][tn][c] = 0.0f;

        auto issue = [&](int b, int k0) {
            #pragma unroll
            for (int v = 0; v < 4; v++) {
                int idx = tid + v * 256;
                int row = idx >> 3, c4 = (idx & 7) * 4;
                cp16(&XS(b, row, c4), &x[(m0 + row) * D_IN + k0 + c4]);
            }
            #pragma unroll
            for (int v = 0; v < 2; v++) {
                int idx = tid + v * 256;
                int kr = idx >> 4, c4 = (idx & 15) * 4;
                cp16(&WS(b, kr, c4), &W[(k0 + kr) * D_OUT + n0 + c4]);
            }
            CP_COMMIT();
        };

        issue(0, 0);
        for (int kc = 0; kc < D_IN / FC_BK; kc++) {
            int cur = kc & 1;
            if (kc < D_IN / FC_BK - 1) { issue(cur ^ 1, (kc + 1) * FC_BK); CP_WAIT1(); }
            else                       { CP_WAIT0(); }
            __syncthreads();

            #pragma unroll
            for (int ks = 0; ks < FC_BK / 8; ks++) {
                int kk = ks * 8;
                unsigned ah[2][4], al[2][4], bh[4][2], bl[4][2];
                #pragma unroll
                for (int tm = 0; tm < 2; tm++) {
                    unsigned af[4];
                    ldsm4(af, sbase + (unsigned)(cur * FC_XW + aoff[tm] + kk) * 4u);
                    #pragma unroll
                    for (int q = 0; q < 4; q++) {
                        float f = __uint_as_float(af[q]);
                        ah[tm][q] = tf32_hi(f);
                        al[tm][q] = __float_as_uint(f - __uint_as_float(ah[tm][q]));
                    }
                }
                #pragma unroll
                for (int tn = 0; tn < 4; tn++) {
                    int c = wn * 32 + tn * 8 + g;
                    float f0 = WS(cur, kk + t,     c);
                    float f1 = WS(cur, kk + t + 4, c);
                    bh[tn][0] = tf32_hi(f0); bl[tn][0] = __float_as_uint(f0 - __uint_as_float(bh[tn][0]));
                    bh[tn][1] = tf32_hi(f1); bl[tn][1] = __float_as_uint(f1 - __uint_as_float(bh[tn][1]));
                }
                #pragma unroll
                for (int tm = 0; tm < 2; tm++)
                    #pragma unroll
                    for (int tn = 0; tn < 4; tn++) {
                        mma_tf32(acc[tm][tn], ah[tm], bh[tn][0], bh[tn][1]);
                        mma_tf32(acc[tm][tn], ah[tm], bl[tn][0], bl[tn][1]);
                        mma_tf32(acc[tm][tn], al[tm], bh[tn][0], bh[tn][1]);
                    }
            }
            __syncthreads();
        }

        float ssum[4] = {0.0f, 0.0f, 0.0f, 0.0f};
        #pragma unroll
        for (int tn = 0; tn < 4; tn++) {
            int c = n0 + wn * 32 + tn * 8 + 2 * t;
            float b0 = bias[c], b1 = bias[c + 1];
            #pragma unroll
            for (int tm = 0; tm < 2; tm++) {
                int r0 = m0 + wm * 32 + tm * 16 + g;
                float o00 = acc[tm][tn][0] + b0, o01 = acc[tm][tn][1] + b1;
                float o10 = acc[tm][tn][2] + b0, o11 = acc[tm][tn][3] + b1;
                *(float2*)&g_h[r0 * D_OUT + c]       = make_float2(o00, o01);
                *(float2*)&g_h[(r0 + 8) * D_OUT + c] = make_float2(o10, o11);
                ssum[tm * 2 + 0] += o00 * o00 + o01 * o01;
                ssum[tm * 2 + 1] += o10 * o10 + o11 * o11;
            }
        }
        #pragma unroll
        for (int rr = 0; rr < 4; rr++) {
            float s = ssum[rr];
            s += __shfl_xor_sync(0xffffffffu, s, 1);
            s += __shfl_xor_sync(0xffffffffu, s, 2);
            if (t == 0) {
                int r = m0 + wm * 32 + (rr >> 1) * 16 + (rr & 1) * 8 + g;
                atomicAdd(&g_sq[r], s);
            }
        }
        __syncthreads();
        __threadfence();                      // publish g_h + g_sq before flag
        if (tid == 0) atomicAdd(&g_fc_done[bid >> 2], 1u);
    }

    // ================= phase 2: dist tiles via ticket queue ==================
    for (;;) {
        __syncthreads();                      // also protects s_sq/s_cl reuse
        if (tid == 0) s_u = atomicAdd(&g_ticket, 1u);
        __syncthreads();
        unsigned u = s_u;
        if (u >= N_TILES) break;

        int row = (int)((sqrtf(8.0f * (float)u + 1.0f) - 1.0f) * 0.5f);
        while ((row + 1) * (row + 2) / 2 <= (int)u) row++;
        while (row * (row + 1) / 2 > (int)u) row--;
        int jt = row, it = (int)u - row * (row + 1) / 2;
        bool do_T = (jt != it);
        int i0 = it * 128, j0 = jt * 128;

        if (tid == 0) {                       // wait for producer groups
            while (atomicAdd(&g_fc_done[it], 0u) < 4u) __nanosleep(128);
            while (atomicAdd(&g_fc_done[jt], 0u) < 4u) __nanosleep(128);
            __threadfence();
        }
        __syncthreads();

        if (tid < 128) {
            s_sq[tid] = __ldcg(&g_sq[j0 + tid]);
            s_cl[tid] = get_cls(targets, j0 + tid, is64);
        }

        int   ci4[4];
        float sqi4[4];
        #pragma unroll
        for (int r = 0; r < 4; r++) {
            int i   = i0 + wm * 32 + (r >> 1) * 16 + (r & 1) * 8 + g;
            ci4[r]  = get_cls(targets, i, is64);
            sqi4[r] = __ldcg(&g_sq[i]);
        }

        float acc[2][8][4];
        #pragma unroll
        for (int tm = 0; tm < 2; tm++)
            #pragma unroll
            for (int tn = 0; tn < 8; tn++)
                #pragma unroll
                for (int c = 0; c < 4; c++) acc[tm][tn][c] = 0.0f;

        auto issue = [&](int b, int k0) {
            #pragma unroll
            for (int v = 0; v < 4; v++) {
                int idx = tid + v * 256;
                int rr = idx >> 3, c4 = (idx & 7) * 4;
                cp16(&AS(b, rr, c4), &g_h[(i0 + rr) * D_OUT + k0 + c4]);
                cp16(&BS(b, rr, c4), &g_h[(j0 + rr) * D_OUT + k0 + c4]);
            }
            CP_COMMIT();
        };

        issue(0, 0);
        #pragma unroll
        for (int kc = 0; kc < D_OUT / D_BK; kc++) {
            int cur = kc & 1;
            if (kc < D_OUT / D_BK - 1) { issue(cur ^ 1, (kc + 1) * D_BK); CP_WAIT1(); }
            else                       { CP_WAIT0(); }
            __syncthreads();

            #pragma unroll
            for (int ks = 0; ks < D_BK / 8; ks++) {
                int kk = ks * 8;
                unsigned a[2][4], b[4][4];
                #pragma unroll
                for (int tm = 0; tm < 2; tm++)
                    ldsm4(a[tm], sbase + (unsigned)(cur * D_TW + aoff[tm] + kk) * 4u);
                #pragma unroll
                for (int tp = 0; tp < 4; tp++)
                    ldsm4(b[tp], sbase + (unsigned)(cur * D_TW + boff[tp] + kk) * 4u);
                #pragma unroll
                for (int tm = 0; tm < 2; tm++)
                    #pragma unroll
                    for (int tn = 0; tn < 8; tn++)
                        mma_tf32(acc[tm][tn], a[tm],
                                 b[tn >> 1][(tn & 1) * 2], b[tn >> 1][(tn & 1) * 2 + 1]);
            }
            __syncthreads();
        }

        float mp[4], mn[4];
        #pragma unroll
        for (int r = 0; r < 4; r++) { mp[r] = -CUDART_INF_F; mn[r] = CUDART_INF_F; }

        #pragma unroll
        for (int tn = 0; tn < 8; tn++) {
            int cc = wn * 64 + tn * 8 + 2 * t;
            float sq1 = s_sq[cc], sq2 = s_sq[cc + 1];
            int   cl1 = s_cl[cc], cl2 = s_cl[cc + 1];
            float tp0 = -CUDART_INF_F, tq0 = CUDART_INF_F;
            float tp1 = -CUDART_INF_F, tq1 = CUDART_INF_F;
            #pragma unroll
            for (int tm = 0; tm < 2; tm++) {
                float a00 = acc[tm][tn][0], a01 = acc[tm][tn][1];
                float a10 = acc[tm][tn][2], a11 = acc[tm][tn][3];
                int r0 = tm * 2, r1 = tm * 2 + 1;
                float v00 = fmaf(-2.0f, a00, sq1);
                float v01 = fmaf(-2.0f, a01, sq2);
                float v10 = fmaf(-2.0f, a10, sq1);
                float v11 = fmaf(-2.0f, a11, sq2);
                if (ci4[r0] == cl1) mp[r0] = fmaxf(mp[r0], v00); else mn[r0] = fminf(mn[r0], v00);
                if (ci4[r0] == cl2) mp[r0] = fmaxf(mp[r0], v01); else mn[r0] = fminf(mn[r0], v01);
                if (ci4[r1] == cl1) mp[r1] = fmaxf(mp[r1], v10); else mn[r1] = fminf(mn[r1], v10);
                if (ci4[r1] == cl2) mp[r1] = fmaxf(mp[r1], v11); else mn[r1] = fminf(mn[r1], v11);
                if (do_T) {
                    float w00 = fmaf(-2.0f, a00, sqi4[r0]);
                    float w01 = fmaf(-2.0f, a01, sqi4[r0]);
                    float w10 = fmaf(-2.0f, a10, sqi4[r1]);
                    float w11 = fmaf(-2.0f, a11, sqi4[r1]);
                    if (ci4[r0] == cl1) tp0 = fmaxf(tp0, w00); else tq0 = fminf(tq0, w00);
                    if (ci4[r0] == cl2) tp1 = fmaxf(tp1, w01); else tq1 = fminf(tq1, w01);
                    if (ci4[r1] == cl1) tp0 = fmaxf(tp0, w10); else tq0 = fminf(tq0, w10);
                    if (ci4[r1] == cl2) tp1 = fmaxf(tp1, w11); else tq1 = fminf(tq1, w11);
                }
            }
            if (do_T) {
                #pragma unroll
                for (int o = 4; o <= 16; o <<= 1) {
                    tp0 = fmaxf(tp0, __shfl_xor_sync(0xffffffffu, tp0, o));
                    tq0 = fminf(tq0, __shfl_xor_sync(0xffffffffu, tq0, o));
                    tp1 = fmaxf(tp1, __shfl_xor_sync(0xffffffffu, tp1, o));
                    tq1 = fminf(tq1, __shfl_xor_sync(0xffffffffu, tq1, o));
                }
                if (g == 0) {
                    atomicMax(&g_hp[j0 + cc],     enc_f(tp0));
                    atomicMax(&g_hn[j0 + cc],     enc_f(-tq0));   // flipped min
                    atomicMax(&g_hp[j0 + cc + 1], enc_f(tp1));
                    atomicMax(&g_hn[j0 + cc + 1], enc_f(-tq1));
                }
            }
        }

        #pragma unroll
        for (int r = 0; r < 4; r++) {
            float p = mp[r], q = mn[r];
            #pragma unroll
            for (int o = 2; o; o >>= 1) {
                p = fmaxf(p, __shfl_xor_sync(0xffffffffu, p, o));
                q = fminf(q, __shfl_xor_sync(0xffffffffu, q, o));
            }
            if (t == 0) {
                int i = i0 + wm * 32 + (r >> 1) * 16 + (r & 1) * 8 + g;
                atomicMax(&g_hp[i], enc_f(p));
                atomicMax(&g_hn[i], enc_f(-q));                  // flipped min
            }
        }
    }

    // ================= phase 3: last finisher computes loss + resets =========
    __syncthreads();
    __threadfence();
    if (tid == 0) s_flag = (atomicAdd(&g_done, 1u) == GRID - 1u) ? 1 : 0;
    __syncthreads();
    if (s_flag) {
        __threadfence();
        __shared__ float red[8];
        float s = 0.0f;
        for (int i = tid; i < N_SAMPLES; i += 256) {
            float sqi = __ldcg(&g_sq[i]);
            float vp  =  dec_f(atomicAdd(&g_hp[i], 0u));
            float vn  = -dec_f(atomicAdd(&g_hn[i], 0u));
            float hp  = sqrtf(fmaxf(sqi + vp, 0.0f));
            float hn  = sqrtf(fmaxf(sqi + vn, 0.0f));
            float xv  = hp - hn;
            s += (xv > 20.0f) ? xv : log1pf(expf(xv));
        }
        #pragma unroll
        for (int o = 16; o; o >>= 1) s += __shfl_xor_sync(0xffffffffu, s, o);
        if (lane == 0) red[tid >> 5] = s;
        __syncthreads();
        if (tid < 32) {
            float v = (tid < 8) ? red[tid] : 0.0f;
            #pragma unroll
            for (int o = 4; o; o >>= 1) v += __shfl_xor_sync(0xffffffffu, v, o);
            if (tid == 0) out[0] = v;
        }
        __syncthreads();
        // reset persistent state for the next (graph-replayed) launch
        for (int i = tid; i < N_SAMPLES; i += 256) {
            g_hp[i] = 0u; g_hn[i] = 0u; g_sq[i] = 0.0f;
        }
        if (tid < 32) g_fc_done[tid] = 0u;
        if (tid == 0) { g_ticket = 0u; g_done = 0u; }
    }
}

// ---------------- launch ----------------------------------------------------
extern "C" void kernel_launch(void* const* d_in, const int* in_sizes, int n_in,
                              void* d_out, int out_size) {
    const float* x  = (const float*)d_in[0];
    const float* W  = (const float*)d_in[1];
    const float* b  = (const float*)d_in[2];
    const void*  tg = d_in[3];

    cudaFuncSetAttribute(k_fused, cudaFuncAttributeMaxDynamicSharedMemorySize, SM_BYTES);
    k_fused<<<GRID, 256, SM_BYTES>>>(x, W, b, tg, (float*)d_out);
}